// round 4
// baseline (speedup 1.0000x reference)
#include <cuda_runtime.h>
#include <cuda_bf16.h>
#include <math.h>

#define GG   512
#define AA   24
#define NN   12288          // GG*AA
#define HID  128
#define TDIM 256
#define BBD  64
#define NL   4

typedef unsigned long long ull;

// ---------------- device scratch (no allocations) ----------------
__device__ float d_h[NN*HID];
__device__ float d_Hs[NN*HID];
__device__ float d_Ht[NN*HID];
__device__ float d_agg[NN*HID];
__device__ float d_S[NN*30];
__device__ float d_C[NN*30];
__device__ float d_T[GG*HID];
__device__ float d_latc[NL*GG*HID];
__device__ float d_Wc[BBD*HID];
__device__ float d_b0[HID];

__device__ __forceinline__ float silu1(float x){ return x * (1.0f/(1.0f+__expf(-x))); }

// ---- packed f32x2 helpers (sm_103a FFMA2 path) ----
__device__ __forceinline__ ull pk2(float x){
  ull r; asm("mov.b64 %0, {%1,%1};" : "=l"(r) : "f"(x)); return r;
}
__device__ __forceinline__ void ffma2(ull& d, ull a, ull b){
  asm("fma.rn.f32x2 %0, %1, %2, %0;" : "+l"(d) : "l"(a), "l"(b));
}
__device__ __forceinline__ float2 up2(ull v){
  float2 r; asm("mov.b64 {%0,%1}, %2;" : "=f"(r.x), "=f"(r.y) : "l"(v)); return r;
}

// ---------- Wc = W_emb @ W_lat[0:128];  b0 = b_emb@W_lat[0:128] + b_lat ----------
__global__ void k_wce(const float* __restrict__ W_emb, const float* __restrict__ b_emb,
                      const float* __restrict__ W_lat, const float* __restrict__ b_lat){
  __shared__ float row[HID];
  int r = blockIdx.x, c = threadIdx.x;
  row[c] = (r < BBD) ? W_emb[r*HID + c] : b_emb[c];
  __syncthreads();
  float s = 0.f;
  #pragma unroll 8
  for (int m = 0; m < HID; m++) s = fmaf(row[m], W_lat[m*HID + c], s);
  if (r < BBD) d_Wc[r*HID + c] = s;
  else         d_b0[c] = s + b_lat[c];
}

// ---------- T[g] = t[g] @ W_lat[144:400] + b0 ----------
__global__ void k_T(const float* __restrict__ t, const float* __restrict__ W_lat){
  __shared__ float ts[TDIM];
  int g = blockIdx.x, c = threadIdx.x;
  ts[c] = t[g*TDIM + c];
  ts[c + HID] = t[g*TDIM + c + HID];
  __syncthreads();
  float s = d_b0[c];
  const float* W = W_lat + 144*HID + c;
  #pragma unroll 8
  for (int k = 0; k < TDIM; k++) s = fmaf(ts[k], W[k*HID], s);
  d_T[g*HID + c] = s;
}

// ---------- latc[l][g] = lattices[g] @ We1[l][256:262] + be1[l] ----------
__global__ void k_latc(const float* __restrict__ lattices, const float* __restrict__ We1,
                       const float* __restrict__ be1){
  int idx = blockIdx.x*blockDim.x + threadIdx.x;
  if (idx >= NL*GG*HID) return;
  int c = idx & (HID-1);
  int g = (idx >> 7) & (GG-1);
  int l = idx >> 16;
  const float* W = We1 + (l*322 + 256)*HID + c;
  const float* la = lattices + g*6;
  float s = be1[l*HID + c];
  #pragma unroll
  for (int d = 0; d < 6; d++) s = fmaf(la[d], W[d*HID], s);
  d_latc[idx] = s;
}

// ---------- node init: h = bb@Wc + so3@W_lat[128:144] + T[g];  S/C tables ----------
__global__ void __launch_bounds__(256) k_init(const float* __restrict__ bb,
      const float* __restrict__ so3, const float* __restrict__ frac,
      const float* __restrict__ W_lat){
  __shared__ float ins[8][80];
  int base = blockIdx.x*8;
  int tid = threadIdx.x;
  for (int it = tid; it < 640; it += 256){
    int n = it/80, p = it - n*80;
    ins[n][p] = (p < BBD) ? bb[(base+n)*BBD + p] : so3[(base+n)*16 + (p-BBD)];
  }
  __syncthreads();
  int half = tid >> 7, c = tid & 127;
  float acc[4];
  #pragma unroll
  for (int n = 0; n < 4; n++){
    int node = base + half*4 + n;
    acc[n] = d_T[(node/AA)*HID + c];
  }
  #pragma unroll 4
  for (int k = 0; k < BBD; k++){
    float w = d_Wc[k*HID + c];
    #pragma unroll
    for (int n = 0; n < 4; n++) acc[n] = fmaf(ins[half*4+n][k], w, acc[n]);
  }
  #pragma unroll
  for (int k = 0; k < 16; k++){
    float w = W_lat[(HID+k)*HID + c];
    #pragma unroll
    for (int n = 0; n < 4; n++) acc[n] = fmaf(ins[half*4+n][BBD+k], w, acc[n]);
  }
  #pragma unroll
  for (int n = 0; n < 4; n++) d_h[(base+half*4+n)*HID + c] = acc[n];
  if (tid < 240){
    int n = tid/30, k = tid - n*30;
    int dd = k/10, f = k - dd*10;
    float x = frac[(base+n)*3 + dd];
    float ang = 6.283185307179586f * (float)f * x;
    float sv, cv; sincosf(ang, &sv, &cv);
    d_S[(base+n)*30 + k] = sv;
    d_C[(base+n)*30 + k] = cv;
  }
}

// ---------- Hs = h@We1[l][0:128],  Ht = h@We1[l][128:256]  (f32x2) ----------
__global__ void __launch_bounds__(256) k_hsht(const float* __restrict__ We1, int l){
  __shared__ float hs[16][HID];
  int base = blockIdx.x*16;
  int tid = threadIdx.x;
  for (int it = tid; it < 16*HID; it += 256){
    int n = it >> 7, k = it & 127;
    hs[n][k] = d_h[(base+n)*HID + k];
  }
  __syncthreads();
  int cg   = tid & 63;          // c pair index
  int c0   = cg*2;
  int half = (tid >> 6) & 1;    // Hs or Ht
  int ng   = tid >> 7;          // node group 0..1, 8 nodes each
  const float* W = We1 + (l*322 + half*HID)*HID;
  ull acc[8];
  #pragma unroll
  for (int n = 0; n < 8; n++) acc[n] = 0ULL;
  #pragma unroll 4
  for (int k = 0; k < HID; k++){
    ull w = *(const ull*)(W + k*HID + c0);
    #pragma unroll
    for (int n = 0; n < 8; n++) ffma2(acc[n], pk2(hs[ng*8+n][k]), w);
  }
  float* outp = half ? d_Ht : d_Hs;
  #pragma unroll
  for (int n = 0; n < 8; n++){
    float2 v = up2(acc[n]);
    *(float2*)(outp + (size_t)(base+ng*8+n)*HID + c0) = v;
  }
}

// ---------- fused edge MLP + mean aggregation (one block per graph) ----------
// smem float offsets
#define E_WE2  0       // 16384
#define E_WD   16384   // 7680
#define E_B2   24064   // 128
#define E_Q    24192   // 3072
#define E_R    27264   // 3072
#define E_S    30336   // 768
#define E_C    31104   // 768
#define E_PEEF 31872   // 12288 : pe=[4][24][64] uses first 6144; ef=[4][24][128] uses all
#define E_G1   44160   // 12288 : [4][24][128]
#define E_TOT  56448   // floats -> 225792 bytes

__global__ void __launch_bounds__(384,1) k_edge(const float* __restrict__ We1,
        const float* __restrict__ We2, const float* __restrict__ be2, int l){
  extern __shared__ float sm[];
  float* We2_s = sm + E_WE2;
  float* Wd_s  = sm + E_WD;
  float* b2_s  = sm + E_B2;
  float* q_s   = sm + E_Q;
  float* r_s   = sm + E_R;
  float* S_s   = sm + E_S;
  float* C_s   = sm + E_C;
  float* pe_s  = sm + E_PEEF;   // first 6144 floats
  float* ef_s  = sm + E_PEEF;   // full 12288 floats (aliases pe after phase B)
  float* g1_s  = sm + E_G1;

  int tid = threadIdx.x;
  int g = blockIdx.x, nb = g*AA;

  for (int it = tid; it < HID*HID; it += 384) We2_s[it] = We2[l*HID*HID + it];
  for (int it = tid; it < 60*HID;  it += 384) Wd_s[it]  = We1[(l*322 + 262)*HID + it];
  if (tid < HID) b2_s[tid] = be2[l*HID + tid];
  const float* latp = d_latc + (l*GG + g)*HID;
  for (int it = tid; it < AA*HID; it += 384){
    q_s[it] = d_Hs[nb*HID + it] + latp[it & 127];
    r_s[it] = d_Ht[nb*HID + it];
  }
  for (int it = tid; it < 720; it += 384){
    int j = it/30, k = it - j*30;
    S_s[j*32 + k] = d_S[(nb+j)*30 + k];
    C_s[j*32 + k] = d_C[(nb+j)*30 + k];
  }
  __syncthreads();

  int cg    = tid & 15;          // c-group: 8 floats each
  int c0    = cg*8;
  int islot = (tid >> 4) & 3;    // i slot 0..3
  int jg    = tid >> 6;          // 0..5 ; j set = {jg, jg+6, jg+12, jg+18}

  for (int ip = 0; ip < 6; ip++){
    int i0 = ip*4;
    // ---- pe for 4 i-slots ----
    for (int it = tid; it < 2880; it += 384){
      int is2 = it / 720;
      int t2 = it - is2*720;
      int j = t2/30, k = t2 - j*30;
      int i = i0 + is2;
      float si = S_s[i*32+k], ci = C_s[i*32+k];
      float sj = S_s[j*32+k], cj = C_s[j*32+k];
      pe_s[is2*1536 + j*64 + k]      = sj*ci - cj*si;
      pe_s[is2*1536 + j*64 + 30 + k] = cj*ci + sj*si;
    }
    __syncthreads();

    // ---- phase B: g1 = silu(q_i + r_j + pe @ Wd) ----
    {
      ull acc[4][4];
      #pragma unroll
      for (int m = 0; m < 4; m++)
        #pragma unroll
        for (int q = 0; q < 4; q++) acc[m][q] = 0ULL;
      const float* pb = pe_s + islot*1536 + jg*64;
      #pragma unroll 3
      for (int k = 0; k < 60; k += 4){
        float4 p0 = *(const float4*)(pb + k);
        float4 p1 = *(const float4*)(pb + 384 + k);
        float4 p2 = *(const float4*)(pb + 768 + k);
        float4 p3 = *(const float4*)(pb + 1152 + k);
        float a0[4] = {p0.x,p0.y,p0.z,p0.w};
        float a1[4] = {p1.x,p1.y,p1.z,p1.w};
        float a2[4] = {p2.x,p2.y,p2.z,p2.w};
        float a3[4] = {p3.x,p3.y,p3.z,p3.w};
        #pragma unroll
        for (int kk = 0; kk < 4; kk++){
          ulonglong2 wa = *(const ulonglong2*)(Wd_s + (k+kk)*HID + c0);
          ulonglong2 wb = *(const ulonglong2*)(Wd_s + (k+kk)*HID + c0 + 4);
          ull pp;
          pp = pk2(a0[kk]); ffma2(acc[0][0],pp,wa.x); ffma2(acc[0][1],pp,wa.y); ffma2(acc[0][2],pp,wb.x); ffma2(acc[0][3],pp,wb.y);
          pp = pk2(a1[kk]); ffma2(acc[1][0],pp,wa.x); ffma2(acc[1][1],pp,wa.y); ffma2(acc[1][2],pp,wb.x); ffma2(acc[1][3],pp,wb.y);
          pp = pk2(a2[kk]); ffma2(acc[2][0],pp,wa.x); ffma2(acc[2][1],pp,wa.y); ffma2(acc[2][2],pp,wb.x); ffma2(acc[2][3],pp,wb.y);
          pp = pk2(a3[kk]); ffma2(acc[3][0],pp,wa.x); ffma2(acc[3][1],pp,wa.y); ffma2(acc[3][2],pp,wb.x); ffma2(acc[3][3],pp,wb.y);
        }
      }
      int i = i0 + islot;
      float4 qa = *(const float4*)(q_s + i*HID + c0);
      float4 qb = *(const float4*)(q_s + i*HID + c0 + 4);
      #pragma unroll
      for (int m = 0; m < 4; m++){
        int j = jg + 6*m;
        float4 ra = *(const float4*)(r_s + j*HID + c0);
        float4 rb = *(const float4*)(r_s + j*HID + c0 + 4);
        float2 v0 = up2(acc[m][0]), v1 = up2(acc[m][1]);
        float2 v2 = up2(acc[m][2]), v3 = up2(acc[m][3]);
        float4 xa, xb;
        xa.x = silu1(qa.x + ra.x + v0.x);
        xa.y = silu1(qa.y + ra.y + v0.y);
        xa.z = silu1(qa.z + ra.z + v1.x);
        xa.w = silu1(qa.w + ra.w + v1.y);
        xb.x = silu1(qb.x + rb.x + v2.x);
        xb.y = silu1(qb.y + rb.y + v2.y);
        xb.z = silu1(qb.z + rb.z + v3.x);
        xb.w = silu1(qb.w + rb.w + v3.y);
        *(float4*)(g1_s + islot*3072 + j*HID + c0) = xa;
        *(float4*)(g1_s + islot*3072 + j*HID + c0 + 4) = xb;
      }
    }
    __syncthreads();

    // ---- phase C: ef = silu(g1 @ We2 + b2) ----
    {
      ull acc[4][4];
      #pragma unroll
      for (int m = 0; m < 4; m++)
        #pragma unroll
        for (int q = 0; q < 4; q++) acc[m][q] = 0ULL;
      const float* gb = g1_s + islot*3072 + jg*HID;
      #pragma unroll 2
      for (int k = 0; k < HID; k += 4){
        float4 p0 = *(const float4*)(gb + k);
        float4 p1 = *(const float4*)(gb + 768 + k);
        float4 p2 = *(const float4*)(gb + 1536 + k);
        float4 p3 = *(const float4*)(gb + 2304 + k);
        float a0[4] = {p0.x,p0.y,p0.z,p0.w};
        float a1[4] = {p1.x,p1.y,p1.z,p1.w};
        float a2[4] = {p2.x,p2.y,p2.z,p2.w};
        float a3[4] = {p3.x,p3.y,p3.z,p3.w};
        #pragma unroll
        for (int kk = 0; kk < 4; kk++){
          ulonglong2 wa = *(const ulonglong2*)(We2_s + (k+kk)*HID + c0);
          ulonglong2 wb = *(const ulonglong2*)(We2_s + (k+kk)*HID + c0 + 4);
          ull pp;
          pp = pk2(a0[kk]); ffma2(acc[0][0],pp,wa.x); ffma2(acc[0][1],pp,wa.y); ffma2(acc[0][2],pp,wb.x); ffma2(acc[0][3],pp,wb.y);
          pp = pk2(a1[kk]); ffma2(acc[1][0],pp,wa.x); ffma2(acc[1][1],pp,wa.y); ffma2(acc[1][2],pp,wb.x); ffma2(acc[1][3],pp,wb.y);
          pp = pk2(a2[kk]); ffma2(acc[2][0],pp,wa.x); ffma2(acc[2][1],pp,wa.y); ffma2(acc[2][2],pp,wb.x); ffma2(acc[2][3],pp,wb.y);
          pp = pk2(a3[kk]); ffma2(acc[3][0],pp,wa.x); ffma2(acc[3][1],pp,wa.y); ffma2(acc[3][2],pp,wb.x); ffma2(acc[3][3],pp,wb.y);
        }
      }
      float4 ba = *(const float4*)(b2_s + c0);
      float4 bb = *(const float4*)(b2_s + c0 + 4);
      #pragma unroll
      for (int m = 0; m < 4; m++){
        int j = jg + 6*m;
        float2 v0 = up2(acc[m][0]), v1 = up2(acc[m][1]);
        float2 v2 = up2(acc[m][2]), v3 = up2(acc[m][3]);
        float4 xa, xb;
        xa.x = silu1(v0.x + ba.x);
        xa.y = silu1(v0.y + ba.y);
        xa.z = silu1(v1.x + ba.z);
        xa.w = silu1(v1.y + ba.w);
        xb.x = silu1(v2.x + bb.x);
        xb.y = silu1(v2.y + bb.y);
        xb.z = silu1(v3.x + bb.z);
        xb.w = silu1(v3.y + bb.w);
        *(float4*)(ef_s + islot*3072 + j*HID + c0) = xa;
        *(float4*)(ef_s + islot*3072 + j*HID + c0 + 4) = xb;
      }
    }
    __syncthreads();

    // ---- mean over j -> agg (4 i's) ----
    for (int it = tid; it < 4*HID; it += 384){
      int is2 = it >> 7, c = it & 127;
      float s = 0.f;
      #pragma unroll
      for (int j = 0; j < AA; j++) s += ef_s[is2*3072 + j*HID + c];
      d_agg[(nb + i0 + is2)*HID + c] = s * (1.0f/24.0f);
    }
    __syncthreads();
  }
}

// ---------- node MLP: h += silu(silu([h,agg]@Wn1+bn1)@Wn2+bn2)  (f32x2) ----------
__global__ void __launch_bounds__(256) k_node(const float* __restrict__ Wn1,
      const float* __restrict__ bn1, const float* __restrict__ Wn2,
      const float* __restrict__ bn2, int l){
  __shared__ float nin[16][256];
  __shared__ float t1s[16][HID];
  int base = blockIdx.x*16;
  int tid = threadIdx.x;
  for (int it = tid; it < 16*256; it += 256){
    int n = it >> 8, k = it & 255;
    nin[n][k] = (k < HID) ? d_h[(base+n)*HID + k] : d_agg[(base+n)*HID + (k-HID)];
  }
  __syncthreads();
  int cg = tid & 63;
  int c0 = cg*2;
  int ng = tid >> 6;            // 0..3, 4 nodes each
  const float* W1 = Wn1 + (size_t)(l*256)*HID;
  ull bb1 = *(const ull*)(bn1 + l*HID + c0);
  ull acc[4];
  #pragma unroll
  for (int n = 0; n < 4; n++) acc[n] = bb1;
  #pragma unroll 4
  for (int k = 0; k < 256; k++){
    ull w = *(const ull*)(W1 + k*HID + c0);
    #pragma unroll
    for (int n = 0; n < 4; n++) ffma2(acc[n], pk2(nin[ng*4+n][k]), w);
  }
  #pragma unroll
  for (int n = 0; n < 4; n++){
    float2 v = up2(acc[n]);
    float2 o; o.x = silu1(v.x); o.y = silu1(v.y);
    *(float2*)(&t1s[ng*4+n][c0]) = o;
  }
  __syncthreads();
  const float* W2 = Wn2 + (size_t)(l*HID)*HID;
  ull bb2 = *(const ull*)(bn2 + l*HID + c0);
  #pragma unroll
  for (int n = 0; n < 4; n++) acc[n] = bb2;
  #pragma unroll 4
  for (int k = 0; k < HID; k++){
    ull w = *(const ull*)(W2 + k*HID + c0);
    #pragma unroll
    for (int n = 0; n < 4; n++) ffma2(acc[n], pk2(t1s[ng*4+n][k]), w);
  }
  #pragma unroll
  for (int n = 0; n < 4; n++){
    int node = base + ng*4 + n;
    float2 v = up2(acc[n]);
    float2 h0 = *(float2*)(d_h + (size_t)node*HID + c0);
    h0.x += silu1(v.x);
    h0.y += silu1(v.y);
    *(float2*)(d_h + (size_t)node*HID + c0) = h0;
  }
}

// ---------- outputs: lattice (G*6), coord (N*3), so3 (N*4) ----------
__global__ void __launch_bounds__(128) k_out(const float* __restrict__ frac,
      const float* __restrict__ W_coord, const float* __restrict__ W_lattice,
      const float* __restrict__ W_so3, float* __restrict__ out){
  __shared__ float hsm[AA*129];
  __shared__ float gf[HID];
  int g = blockIdx.x, nb = g*AA;
  int tid = threadIdx.x;
  for (int it = tid; it < AA*HID; it += 128){
    int n = it >> 7, k = it & 127;
    hsm[n*129 + k] = d_h[(nb+n)*HID + k];
  }
  __syncthreads();
  {
    float s = 0.f;
    #pragma unroll
    for (int n = 0; n < AA; n++) s += hsm[n*129 + tid];
    gf[tid] = s * (1.0f/24.0f);
  }
  __syncthreads();
  if (tid < 6){
    float s = 0.f;
    #pragma unroll 8
    for (int k = 0; k < HID; k++) s = fmaf(gf[k], W_lattice[k*6 + tid], s);
    out[g*6 + tid] = s;
  }
  if (tid < AA){
    int n = tid;
    const float* hr = hsm + n*129;
    #pragma unroll
    for (int o = 0; o < 3; o++){
      float s = 0.f;
      #pragma unroll 8
      for (int k = 0; k < HID; k++) s = fmaf(hr[k], W_coord[k*3 + o], s);
      float v = s + frac[(nb+n)*3 + o];
      out[GG*6 + (nb+n)*3 + o] = v - floorf(v);
    }
    float so[4];
    #pragma unroll
    for (int o = 0; o < 4; o++){
      float s = 0.f;
      #pragma unroll 8
      for (int k = 0; k < HID; k++) s = fmaf(hr[k], W_so3[k*4 + o], s);
      so[o] = s;
    }
    float nrm = sqrtf(so[0]*so[0] + so[1]*so[1] + so[2]*so[2] + so[3]*so[3]);
    float inv = 1.0f / nrm;
    #pragma unroll
    for (int o = 0; o < 4; o++)
      out[GG*6 + NN*3 + (nb+n)*4 + o] = so[o] * inv;
  }
}

extern "C" void kernel_launch(void* const* d_in, const int* in_sizes, int n_in,
                              void* d_out, int out_size){
  const float* t      = (const float*)d_in[0];
  const float* bb     = (const float*)d_in[1];
  const float* frac   = (const float*)d_in[2];
  const float* so3    = (const float*)d_in[3];
  const float* latt   = (const float*)d_in[4];
  const float* W_emb  = (const float*)d_in[8];
  const float* b_emb  = (const float*)d_in[9];
  const float* W_lat  = (const float*)d_in[10];
  const float* b_lat  = (const float*)d_in[11];
  const float* We1    = (const float*)d_in[12];
  const float* be1    = (const float*)d_in[13];
  const float* We2    = (const float*)d_in[14];
  const float* be2    = (const float*)d_in[15];
  const float* Wn1    = (const float*)d_in[16];
  const float* bn1    = (const float*)d_in[17];
  const float* Wn2    = (const float*)d_in[18];
  const float* bn2    = (const float*)d_in[19];
  const float* W_coord   = (const float*)d_in[20];
  const float* W_lattice = (const float*)d_in[21];
  const float* W_so3     = (const float*)d_in[22];
  float* out = (float*)d_out;

  cudaFuncSetAttribute(k_edge, cudaFuncAttributeMaxDynamicSharedMemorySize,
                       E_TOT * (int)sizeof(float));

  k_wce <<<BBD+1, 128>>>(W_emb, b_emb, W_lat, b_lat);
  k_T   <<<GG, 128>>>(t, W_lat);
  k_latc<<<(NL*GG*HID)/256, 256>>>(latt, We1, be1);
  k_init<<<NN/8, 256>>>(bb, so3, frac, W_lat);
  for (int l = 0; l < NL; l++){
    k_hsht<<<NN/16, 256>>>(We1, l);
    k_edge<<<GG, 384, E_TOT*(int)sizeof(float)>>>(We1, We2, be2, l);
    k_node<<<NN/16, 256>>>(Wn1, bn1, Wn2, bn2, l);
  }
  k_out<<<GG, 128>>>(frac, W_coord, W_lattice, W_so3, out);
}

// round 5
// speedup vs baseline: 1.2017x; 1.2017x over previous
#include <cuda_runtime.h>
#include <cuda_bf16.h>
#include <math.h>

#define GG   512
#define AA   24
#define NN   12288          // GG*AA
#define HID  128
#define TDIM 256
#define BBD  64
#define NL   4

// ---------------- device scratch (no allocations) ----------------
__device__ float d_h[NN*HID];
__device__ float d_Hs[NN*HID];
__device__ float d_Ht[NN*HID];
__device__ float d_agg[NN*HID];
__device__ float d_S[NN*30];
__device__ float d_C[NN*30];
__device__ float d_T[GG*HID];
__device__ float d_latc[NL*GG*HID];
__device__ float d_Wc[BBD*HID];
__device__ float d_b0[HID];

__device__ __forceinline__ float silu1(float x){ return x * (1.0f/(1.0f+__expf(-x))); }
__device__ __forceinline__ void fmas(float4& a, float p, const float4 w){
  a.x = fmaf(p, w.x, a.x); a.y = fmaf(p, w.y, a.y);
  a.z = fmaf(p, w.z, a.z); a.w = fmaf(p, w.w, a.w);
}

// ---------- Wc = W_emb @ W_lat[0:128];  b0 = b_emb@W_lat[0:128] + b_lat ----------
__global__ void k_wce(const float* __restrict__ W_emb, const float* __restrict__ b_emb,
                      const float* __restrict__ W_lat, const float* __restrict__ b_lat){
  __shared__ float row[HID];
  int r = blockIdx.x, c = threadIdx.x;
  row[c] = (r < BBD) ? W_emb[r*HID + c] : b_emb[c];
  __syncthreads();
  float s = 0.f;
  #pragma unroll 8
  for (int m = 0; m < HID; m++) s = fmaf(row[m], W_lat[m*HID + c], s);
  if (r < BBD) d_Wc[r*HID + c] = s;
  else         d_b0[c] = s + b_lat[c];
}

// ---------- T[g] = t[g] @ W_lat[144:400] + b0 ----------
__global__ void k_T(const float* __restrict__ t, const float* __restrict__ W_lat){
  __shared__ float ts[TDIM];
  int g = blockIdx.x, c = threadIdx.x;
  ts[c] = t[g*TDIM + c];
  ts[c + HID] = t[g*TDIM + c + HID];
  __syncthreads();
  float s = d_b0[c];
  const float* W = W_lat + 144*HID + c;
  #pragma unroll 8
  for (int k = 0; k < TDIM; k++) s = fmaf(ts[k], W[k*HID], s);
  d_T[g*HID + c] = s;
}

// ---------- latc[l][g] = lattices[g] @ We1[l][256:262] + be1[l] ----------
__global__ void k_latc(const float* __restrict__ lattices, const float* __restrict__ We1,
                       const float* __restrict__ be1){
  int idx = blockIdx.x*blockDim.x + threadIdx.x;
  if (idx >= NL*GG*HID) return;
  int c = idx & (HID-1);
  int g = (idx >> 7) & (GG-1);
  int l = idx >> 16;
  const float* W = We1 + (l*322 + 256)*HID + c;
  const float* la = lattices + g*6;
  float s = be1[l*HID + c];
  #pragma unroll
  for (int d = 0; d < 6; d++) s = fmaf(la[d], W[d*HID], s);
  d_latc[idx] = s;
}

// ---------- node init: h = bb@Wc + so3@W_lat[128:144] + T[g];  S/C tables ----------
__global__ void __launch_bounds__(256) k_init(const float* __restrict__ bb,
      const float* __restrict__ so3, const float* __restrict__ frac,
      const float* __restrict__ W_lat){
  __shared__ float ins[8][80];
  int base = blockIdx.x*8;
  int tid = threadIdx.x;
  for (int it = tid; it < 640; it += 256){
    int n = it/80, p = it - n*80;
    ins[n][p] = (p < BBD) ? bb[(base+n)*BBD + p] : so3[(base+n)*16 + (p-BBD)];
  }
  __syncthreads();
  int half = tid >> 7, c = tid & 127;
  float acc[4];
  #pragma unroll
  for (int n = 0; n < 4; n++){
    int node = base + half*4 + n;
    acc[n] = d_T[(node/AA)*HID + c];
  }
  #pragma unroll 4
  for (int k = 0; k < BBD; k++){
    float w = d_Wc[k*HID + c];
    #pragma unroll
    for (int n = 0; n < 4; n++) acc[n] = fmaf(ins[half*4+n][k], w, acc[n]);
  }
  #pragma unroll
  for (int k = 0; k < 16; k++){
    float w = W_lat[(HID+k)*HID + c];
    #pragma unroll
    for (int n = 0; n < 4; n++) acc[n] = fmaf(ins[half*4+n][BBD+k], w, acc[n]);
  }
  #pragma unroll
  for (int n = 0; n < 4; n++) d_h[(base+half*4+n)*HID + c] = acc[n];
  if (tid < 240){
    int n = tid/30, k = tid - n*30;
    int dd = k/10, f = k - dd*10;
    float x = frac[(base+n)*3 + dd];
    float ang = 6.283185307179586f * (float)f * x;
    float sv, cv; sincosf(ang, &sv, &cv);
    d_S[(base+n)*30 + k] = sv;
    d_C[(base+n)*30 + k] = cv;
  }
}

// ---------- Hs = h@We1[l][0:128],  Ht = h@We1[l][128:256] ----------
__global__ void __launch_bounds__(256) k_hsht(const float* __restrict__ We1, int l){
  __shared__ float hs[8][HID];
  int base = blockIdx.x*8;
  int tid = threadIdx.x;
  for (int it = tid; it < 1024; it += 256){
    int n = it >> 7, k = it & 127;
    hs[n][k] = d_h[(base+n)*HID + k];
  }
  __syncthreads();
  int half = tid >> 7, c = tid & 127;
  const float* W = We1 + (l*322 + half*HID)*HID + c;
  float acc[8] = {0,0,0,0,0,0,0,0};
  #pragma unroll 4
  for (int k = 0; k < HID; k++){
    float w = W[k*HID];
    #pragma unroll
    for (int n = 0; n < 8; n++) acc[n] = fmaf(hs[n][k], w, acc[n]);
  }
  float* outp = half ? d_Ht : d_Hs;
  #pragma unroll
  for (int n = 0; n < 8; n++) outp[(base+n)*HID + c] = acc[n];
}

// ---------- fused edge MLP + mean aggregation (2 blocks per graph) ----------
// smem float offsets
#define E_WE2 0
#define E_WD  16384
#define E_B2  24064
#define E_Q   24192
#define E_R   27264
#define E_S   30336
#define E_C   31104
#define E_PE  31872   // [2][24][64]
#define E_G1  34944   // [2][24][128]
#define E_EF  41088   // [2][24][128]
#define E_TOT 47232   // floats -> 188928 bytes

__global__ void __launch_bounds__(384,1) k_edge(const float* __restrict__ We1,
        const float* __restrict__ We2, const float* __restrict__ be2, int l){
  extern __shared__ float sm[];
  float* We2_s = sm + E_WE2;
  float* Wd_s  = sm + E_WD;
  float* b2_s  = sm + E_B2;
  float* q_s   = sm + E_Q;
  float* r_s   = sm + E_R;
  float* S_s   = sm + E_S;
  float* C_s   = sm + E_C;
  float* pe_s  = sm + E_PE;
  float* g1_s  = sm + E_G1;
  float* ef_s  = sm + E_EF;

  int tid = threadIdx.x;
  int g = blockIdx.x >> 1;           // graph
  int ihalf = blockIdx.x & 1;        // which 12 i-atoms this block owns
  int nb = g*AA;

  for (int it = tid; it < HID*HID; it += 384) We2_s[it] = We2[l*HID*HID + it];
  for (int it = tid; it < 60*HID;  it += 384) Wd_s[it]  = We1[(l*322 + 262)*HID + it];
  if (tid < HID) b2_s[tid] = be2[l*HID + tid];
  const float* latp = d_latc + (l*GG + g)*HID;
  for (int it = tid; it < AA*HID; it += 384){
    q_s[it] = d_Hs[nb*HID + it] + latp[it & 127];
    r_s[it] = d_Ht[nb*HID + it];
  }
  for (int it = tid; it < 720; it += 384){
    int j = it/30, k = it - j*30;
    S_s[j*32 + k] = d_S[(nb+j)*30 + k];
    C_s[j*32 + k] = d_C[(nb+j)*30 + k];
  }
  __syncthreads();

  int c0 = (tid & 31) * 4;
  int islot = (tid >> 5) & 1;
  int jg = tid >> 6;                 // 0..5 ; j set = {jg, jg+6, jg+12, jg+18}

  for (int ip = 0; ip < 6; ip++){
    int i0 = ihalf*12 + ip*2;
    // pe for both i-slots
    for (int it = tid; it < 1440; it += 384){
      int is2 = (it >= 720) ? 1 : 0;
      int t2 = it - is2*720;
      int j = t2/30, k = t2 - j*30;
      int i = i0 + is2;
      float si = S_s[i*32+k], ci = C_s[i*32+k];
      float sj = S_s[j*32+k], cj = C_s[j*32+k];
      pe_s[is2*1536 + j*64 + k]      = sj*ci - cj*si;
      pe_s[is2*1536 + j*64 + 30 + k] = cj*ci + sj*si;
    }
    __syncthreads();

    // phase B: pe @ Wd  -> g1 = silu(q_i + r_j + .)
    {
      float4 a0 = make_float4(0,0,0,0), a1 = a0, a2 = a0, a3 = a0;
      const float* pb = pe_s + islot*1536 + jg*64;
      #pragma unroll 3
      for (int k = 0; k < 60; k += 4){
        float4 p0 = *(const float4*)(pb + k);
        float4 p1 = *(const float4*)(pb + 6*64 + k);
        float4 p2 = *(const float4*)(pb + 12*64 + k);
        float4 p3 = *(const float4*)(pb + 18*64 + k);
        float q0[4] = {p0.x,p0.y,p0.z,p0.w};
        float q1[4] = {p1.x,p1.y,p1.z,p1.w};
        float q2[4] = {p2.x,p2.y,p2.z,p2.w};
        float q3[4] = {p3.x,p3.y,p3.z,p3.w};
        #pragma unroll
        for (int kk = 0; kk < 4; kk++){
          float4 w = *(const float4*)(Wd_s + (k+kk)*HID + c0);
          fmas(a0, q0[kk], w); fmas(a1, q1[kk], w);
          fmas(a2, q2[kk], w); fmas(a3, q3[kk], w);
        }
      }
      int i = i0 + islot;
      float4 qv = *(const float4*)(q_s + i*HID + c0);
      float4 acc[4] = {a0,a1,a2,a3};
      #pragma unroll
      for (int m = 0; m < 4; m++){
        int j = jg + 6*m;
        float4 rv = *(const float4*)(r_s + j*HID + c0);
        float4 x;
        x.x = silu1(qv.x + rv.x + acc[m].x);
        x.y = silu1(qv.y + rv.y + acc[m].y);
        x.z = silu1(qv.z + rv.z + acc[m].z);
        x.w = silu1(qv.w + rv.w + acc[m].w);
        *(float4*)(g1_s + islot*3072 + j*HID + c0) = x;
      }
    }
    __syncthreads();

    // phase C: g1 @ We2 + b2 -> ef = silu(.)
    {
      float4 a0 = make_float4(0,0,0,0), a1 = a0, a2 = a0, a3 = a0;
      const float* gb = g1_s + islot*3072 + jg*HID;
      #pragma unroll 4
      for (int k = 0; k < HID; k += 4){
        float4 p0 = *(const float4*)(gb + k);
        float4 p1 = *(const float4*)(gb + 6*HID + k);
        float4 p2 = *(const float4*)(gb + 12*HID + k);
        float4 p3 = *(const float4*)(gb + 18*HID + k);
        float q0[4] = {p0.x,p0.y,p0.z,p0.w};
        float q1[4] = {p1.x,p1.y,p1.z,p1.w};
        float q2[4] = {p2.x,p2.y,p2.z,p2.w};
        float q3[4] = {p3.x,p3.y,p3.z,p3.w};
        #pragma unroll
        for (int kk = 0; kk < 4; kk++){
          float4 w = *(const float4*)(We2_s + (k+kk)*HID + c0);
          fmas(a0, q0[kk], w); fmas(a1, q1[kk], w);
          fmas(a2, q2[kk], w); fmas(a3, q3[kk], w);
        }
      }
      float4 bv = *(const float4*)(b2_s + c0);
      float4 acc[4] = {a0,a1,a2,a3};
      #pragma unroll
      for (int m = 0; m < 4; m++){
        int j = jg + 6*m;
        float4 x;
        x.x = silu1(acc[m].x + bv.x);
        x.y = silu1(acc[m].y + bv.y);
        x.z = silu1(acc[m].z + bv.z);
        x.w = silu1(acc[m].w + bv.w);
        *(float4*)(ef_s + islot*3072 + j*HID + c0) = x;
      }
    }
    __syncthreads();

    // mean over j -> agg
    if (tid < 256){
      int is2 = tid >> 7, c = tid & 127;
      float s = 0.f;
      #pragma unroll
      for (int j = 0; j < AA; j++) s += ef_s[is2*3072 + j*HID + c];
      d_agg[(nb + i0 + is2)*HID + c] = s * (1.0f/24.0f);
    }
    __syncthreads();
  }
}

// ---------- node MLP: h += silu(silu([h,agg]@Wn1+bn1)@Wn2+bn2) ----------
__global__ void __launch_bounds__(256) k_node(const float* __restrict__ Wn1,
      const float* __restrict__ bn1, const float* __restrict__ Wn2,
      const float* __restrict__ bn2, int l){
  __shared__ float nin[8][256];
  __shared__ float t1s[8][HID];
  int base = blockIdx.x*8;
  int tid = threadIdx.x;
  for (int it = tid; it < 8*256; it += 256){
    int n = it >> 8, k = it & 255;
    nin[n][k] = (k < HID) ? d_h[(base+n)*HID + k] : d_agg[(base+n)*HID + (k-HID)];
  }
  __syncthreads();
  int half = tid >> 7, c = tid & 127;
  float acc[4];
  float b1 = bn1[l*HID + c];
  #pragma unroll
  for (int n = 0; n < 4; n++) acc[n] = b1;
  const float* W1 = Wn1 + (l*256)*HID + c;
  #pragma unroll 4
  for (int k = 0; k < 256; k++){
    float w = W1[k*HID];
    #pragma unroll
    for (int n = 0; n < 4; n++) acc[n] = fmaf(nin[half*4+n][k], w, acc[n]);
  }
  #pragma unroll
  for (int n = 0; n < 4; n++) t1s[half*4+n][c] = silu1(acc[n]);
  __syncthreads();
  float b2 = bn2[l*HID + c];
  #pragma unroll
  for (int n = 0; n < 4; n++) acc[n] = b2;
  const float* W2 = Wn2 + (l*HID)*HID + c;
  #pragma unroll 4
  for (int k = 0; k < HID; k++){
    float w = W2[k*HID];
    #pragma unroll
    for (int n = 0; n < 4; n++) acc[n] = fmaf(t1s[half*4+n][k], w, acc[n]);
  }
  #pragma unroll
  for (int n = 0; n < 4; n++){
    int node = base + half*4 + n;
    d_h[node*HID + c] += silu1(acc[n]);
  }
}

// ---------- outputs: lattice (G*6), coord (N*3), so3 (N*4) ----------
__global__ void __launch_bounds__(128) k_out(const float* __restrict__ frac,
      const float* __restrict__ W_coord, const float* __restrict__ W_lattice,
      const float* __restrict__ W_so3, float* __restrict__ out){
  __shared__ float hsm[AA*129];
  __shared__ float gf[HID];
  int g = blockIdx.x, nb = g*AA;
  int tid = threadIdx.x;
  for (int it = tid; it < AA*HID; it += 128){
    int n = it >> 7, k = it & 127;
    hsm[n*129 + k] = d_h[(nb+n)*HID + k];
  }
  __syncthreads();
  {
    float s = 0.f;
    #pragma unroll
    for (int n = 0; n < AA; n++) s += hsm[n*129 + tid];
    gf[tid] = s * (1.0f/24.0f);
  }
  __syncthreads();
  if (tid < 6){
    float s = 0.f;
    #pragma unroll 8
    for (int k = 0; k < HID; k++) s = fmaf(gf[k], W_lattice[k*6 + tid], s);
    out[g*6 + tid] = s;
  }
  if (tid < AA){
    int n = tid;
    const float* hr = hsm + n*129;
    #pragma unroll
    for (int o = 0; o < 3; o++){
      float s = 0.f;
      #pragma unroll 8
      for (int k = 0; k < HID; k++) s = fmaf(hr[k], W_coord[k*3 + o], s);
      float v = s + frac[(nb+n)*3 + o];
      out[GG*6 + (nb+n)*3 + o] = v - floorf(v);
    }
    float so[4];
    #pragma unroll
    for (int o = 0; o < 4; o++){
      float s = 0.f;
      #pragma unroll 8
      for (int k = 0; k < HID; k++) s = fmaf(hr[k], W_so3[k*4 + o], s);
      so[o] = s;
    }
    float nrm = sqrtf(so[0]*so[0] + so[1]*so[1] + so[2]*so[2] + so[3]*so[3]);
    float inv = 1.0f / nrm;
    #pragma unroll
    for (int o = 0; o < 4; o++)
      out[GG*6 + NN*3 + (nb+n)*4 + o] = so[o] * inv;
  }
}

extern "C" void kernel_launch(void* const* d_in, const int* in_sizes, int n_in,
                              void* d_out, int out_size){
  const float* t      = (const float*)d_in[0];
  const float* bb     = (const float*)d_in[1];
  const float* frac   = (const float*)d_in[2];
  const float* so3    = (const float*)d_in[3];
  const float* latt   = (const float*)d_in[4];
  const float* W_emb  = (const float*)d_in[8];
  const float* b_emb  = (const float*)d_in[9];
  const float* W_lat  = (const float*)d_in[10];
  const float* b_lat  = (const float*)d_in[11];
  const float* We1    = (const float*)d_in[12];
  const float* be1    = (const float*)d_in[13];
  const float* We2    = (const float*)d_in[14];
  const float* be2    = (const float*)d_in[15];
  const float* Wn1    = (const float*)d_in[16];
  const float* bn1    = (const float*)d_in[17];
  const float* Wn2    = (const float*)d_in[18];
  const float* bn2    = (const float*)d_in[19];
  const float* W_coord   = (const float*)d_in[20];
  const float* W_lattice = (const float*)d_in[21];
  const float* W_so3     = (const float*)d_in[22];
  float* out = (float*)d_out;

  cudaFuncSetAttribute(k_edge, cudaFuncAttributeMaxDynamicSharedMemorySize,
                       E_TOT * (int)sizeof(float));

  k_wce <<<BBD+1, 128>>>(W_emb, b_emb, W_lat, b_lat);
  k_T   <<<GG, 128>>>(t, W_lat);
  k_latc<<<(NL*GG*HID)/256, 256>>>(latt, We1, be1);
  k_init<<<NN/8, 256>>>(bb, so3, frac, W_lat);
  for (int l = 0; l < NL; l++){
    k_hsht<<<NN/8, 256>>>(We1, l);
    k_edge<<<GG*2, 384, E_TOT*(int)sizeof(float)>>>(We1, We2, be2, l);
    k_node<<<NN/8, 256>>>(Wn1, bn1, Wn2, bn2, l);
  }
  k_out<<<GG, 128>>>(frac, W_coord, W_lattice, W_so3, out);
}